// round 3
// baseline (speedup 1.0000x reference)
#include <cuda_runtime.h>

#define N_ROWS 16384
#define D      2048
#define NUM_LABELS 1024
#define NUM_CAMS   8
#define S (NUM_LABELS * NUM_CAMS)   // 8192 segments

// ---- scratch (device globals; no allocation allowed) ----
__device__ int    g_seg[N_ROWS];
__device__ int    g_count[S];
__device__ int    g_offset[S];
__device__ int    g_cursor[S];
__device__ int    g_order[N_ROWS];
__device__ int    g_is64;
__device__ double g_partial[S];

// ---------------------------------------------------------------------------
// K0: zero counts/cursors + detect int64 vs int32 storage of labels/cam_ids.
// If the arrays are int64 (little-endian, values < 2^31), every odd int32 word
// is 0. If int32, cam_ids (0..7) has nonzero odd positions w.p. 1 - 8^-2048.
// ---------------------------------------------------------------------------
__global__ void k_init(const int* __restrict__ cam32) {
    int idx = blockIdx.x * blockDim.x + threadIdx.x;
    if (idx < S) { g_count[idx] = 0; g_cursor[idx] = 0; }
    if (blockIdx.x == 0) {
        __shared__ int any;
        if (threadIdx.x == 0) any = 0;
        __syncthreads();
        int local = 0;
        for (int i = threadIdx.x; i < 2048; i += 256)
            local |= cam32[2 * i + 1];
        if (local) atomicOr(&any, 1);
        __syncthreads();
        if (threadIdx.x == 0) g_is64 = any ? 0 : 1;
    }
}

// K1: segment id per row + histogram
__global__ void k_build(const int* __restrict__ lab32, const int* __restrict__ cam32) {
    int i = blockIdx.x * blockDim.x + threadIdx.x;
    if (i >= N_ROWS) return;
    int stride = g_is64 ? 2 : 1;
    int lab = lab32[i * stride];
    int cam = cam32[i * stride];
    int seg = lab * NUM_CAMS + cam;
    g_seg[i] = seg;
    atomicAdd(&g_count[seg], 1);
}

// K2: exclusive prefix sum over the 8192 counts (one block, 1024 threads, 8/thread)
__global__ void k_scan() {
    __shared__ int tsum[1024];
    int t = threadIdx.x;
    int base = t * 8;
    int local[8];
    int run = 0;
#pragma unroll
    for (int j = 0; j < 8; j++) { local[j] = run; run += g_count[base + j]; }
    tsum[t] = run;
    __syncthreads();
    // Hillis-Steele inclusive scan over thread totals
    for (int off = 1; off < 1024; off <<= 1) {
        int v = (t >= off) ? tsum[t - off] : 0;
        __syncthreads();
        tsum[t] += v;
        __syncthreads();
    }
    int ex = (t == 0) ? 0 : tsum[t - 1];
#pragma unroll
    for (int j = 0; j < 8; j++) g_offset[base + j] = ex + local[j];
}

// K3: scatter row indices into segment-sorted order
__global__ void k_scatter() {
    int i = blockIdx.x * blockDim.x + threadIdx.x;
    if (i >= N_ROWS) return;
    int seg = g_seg[i];
    int pos = g_offset[seg] + atomicAdd(&g_cursor[seg], 1);
    g_order[pos] = i;
}

__device__ __forceinline__ float sl1(float d) {
    float ad = fabsf(d);
    return ad < 1.0f ? 0.5f * d * d : ad - 0.5f;
}

// K4: one CTA per segment — compute mean, then SmoothL1 vs mean, block-reduce.
// cnt==0: no rows. cnt==1: mean == row -> zero loss, skip entirely.
__global__ __launch_bounds__(256) void k_main(const float* __restrict__ feats) {
    int s = blockIdx.x;
    int t = threadIdx.x;
    int cnt = g_count[s];
    if (cnt <= 1) { if (t == 0) g_partial[s] = 0.0; return; }
    int base = g_offset[s];

    // thread t owns cols [4t,4t+4) and [1024+4t,1024+4t+4) (two coalesced float4)
    float4 s0 = make_float4(0.f, 0.f, 0.f, 0.f);
    float4 s1 = make_float4(0.f, 0.f, 0.f, 0.f);
    for (int r = 0; r < cnt; r++) {
        int row = g_order[base + r];
        const float4* p = (const float4*)(feats + (size_t)row * D);
        float4 a = p[t];
        float4 b = p[t + 256];
        s0.x += a.x; s0.y += a.y; s0.z += a.z; s0.w += a.w;
        s1.x += b.x; s1.y += b.y; s1.z += b.z; s1.w += b.w;
    }
    float inv = 1.0f / (float)cnt;
    float4 m0 = make_float4(s0.x * inv, s0.y * inv, s0.z * inv, s0.w * inv);
    float4 m1 = make_float4(s1.x * inv, s1.y * inv, s1.z * inv, s1.w * inv);

    float acc = 0.f;
    for (int r = 0; r < cnt; r++) {
        int row = g_order[base + r];
        const float4* p = (const float4*)(feats + (size_t)row * D);
        float4 a = p[t];          // L1/L2 hit — just read in pass 1
        float4 b = p[t + 256];
        acc += sl1(a.x - m0.x) + sl1(a.y - m0.y) + sl1(a.z - m0.z) + sl1(a.w - m0.w);
        acc += sl1(b.x - m1.x) + sl1(b.y - m1.y) + sl1(b.z - m1.z) + sl1(b.w - m1.w);
    }

    // block reduce (8 warps)
#pragma unroll
    for (int off = 16; off; off >>= 1)
        acc += __shfl_down_sync(0xffffffffu, acc, off);
    __shared__ float wsum[8];
    if ((t & 31) == 0) wsum[t >> 5] = acc;
    __syncthreads();
    if (t == 0) {
        float tot = 0.f;
#pragma unroll
        for (int w = 0; w < 8; w++) tot += wsum[w];
        g_partial[s] = (double)tot;
    }
}

// K5: deterministic final reduction of 8192 doubles -> scalar mean
__global__ void k_final(float* __restrict__ out) {
    __shared__ double red[1024];
    int t = threadIdx.x;
    double local = 0.0;
    for (int i = t; i < S; i += 1024) local += g_partial[i];
    red[t] = local;
    __syncthreads();
    for (int off = 512; off; off >>= 1) {
        if (t < off) red[t] += red[t + off];
        __syncthreads();
    }
    if (t == 0) out[0] = (float)(red[0] / ((double)N_ROWS * (double)D));
}

extern "C" void kernel_launch(void* const* d_in, const int* in_sizes, int n_in,
                              void* d_out, int out_size) {
    const float* feats = (const float*)d_in[0];
    const int*   lab32 = (const int*)d_in[1];
    const int*   cam32 = (const int*)d_in[2];
    float* out = (float*)d_out;

    k_init   <<<(S + 255) / 256, 256>>>(cam32);
    k_build  <<<(N_ROWS + 255) / 256, 256>>>(lab32, cam32);
    k_scan   <<<1, 1024>>>();
    k_scatter<<<(N_ROWS + 255) / 256, 256>>>();
    k_main   <<<S, 256>>>(feats);
    k_final  <<<1, 1024>>>(out);
}